// round 7
// baseline (speedup 1.0000x reference)
#include <cuda_runtime.h>

// Problem constants (fixed by reference setup_inputs)
#define Hh     32
#define EPB    2          // batch elements per block
#define TIN    999        // teacher-forced input length
#define TFE    998        // TF steps handled in the TF loop (last TF step runs in gen loop)
#define STEPS  1999       // TIN + future(1000)
#define BATCH  1024

typedef unsigned long long u64;

// Scratch: h2 history for the teacher-forced phase (head applied by head_kernel)
__device__ float H2g[(size_t)BATCH * TFE * Hh];   // ~128 MB static scratch (allowed)

// Packed 2xfp32 FMA / ADD (sm_103a f32x2 pipe)
__device__ __forceinline__ u64 fma2(u64 a, u64 b, u64 c) {
    u64 d;
    asm("fma.rn.f32x2 %0, %1, %2, %3;" : "=l"(d) : "l"(a), "l"(b), "l"(c));
    return d;
}
__device__ __forceinline__ u64 add2(u64 a, u64 b) {
    u64 d;
    asm("add.rn.f32x2 %0, %1, %2;" : "=l"(d) : "l"(a), "l"(b));
    return d;
}
__device__ __forceinline__ float f2lo(u64 a) { return __uint_as_float((unsigned)a); }
__device__ __forceinline__ float f2hi(u64 a) { return __uint_as_float((unsigned)(a >> 32)); }

__device__ __forceinline__ float ex2a(float x) { float y; asm("ex2.approx.f32 %0, %1;" : "=f"(y) : "f"(x)); return y; }
__device__ __forceinline__ float rcpa(float x) { float y; asm("rcp.approx.f32 %0, %1;" : "=f"(y) : "f"(x)); return y; }

// sigmoid(x) = 1/(1 + 2^(-x*log2e)); ~1e-7 accurate
__device__ __forceinline__ float sigm(float x) {
    return rcpa(1.0f + ex2a(-1.4426950408889634f * x));
}
// tanh(x) = 1 - 2/(1 + 2^(2x*log2e)); ~1e-7 accurate
__device__ __forceinline__ float tanh_(float x) {
    return fmaf(-2.0f, rcpa(1.0f + ex2a(2.8853900817779268f * x)), 1.0f);
}

__global__ __launch_bounds__(128) void lstm_seq_kernel(
    const float* __restrict__ input,
    const float* __restrict__ W_ih1, const float* __restrict__ W_hh1,
    const float* __restrict__ b_ih1, const float* __restrict__ b_hh1,
    const float* __restrict__ W_ih2, const float* __restrict__ W_hh2,
    const float* __restrict__ b_ih2, const float* __restrict__ b_hh2,
    const float* __restrict__ W_lin, const float* __restrict__ b_lin,
    float* __restrict__ out)
{
    __shared__ float sh_in[EPB][TIN];
    __shared__ __align__(16) float sh_h1[EPB][Hh];
    __shared__ __align__(16) float sh_h2[EPB][Hh];
    __shared__ float sh_zA[EPB][4 * Hh];
    __shared__ float sh_zB[EPB][4 * Hh];
    __shared__ __align__(16) float sh_p[EPB][4];     // per-warp head partials (gen)

    const int r  = threadIdx.x;          // gate row 0..127
    const int w  = r >> 5;               // warp 0..3
    const int l  = r & 31;               // lane
    const int b0 = blockIdx.x * EPB;

    // Combine-task mapping: spread 64 tasks over all 4 warps (lanes < 16)
    const int  tau  = l * 4 + w;         // 0..63 for l<16
    const int  te   = tau >> 5;          // element 0/1
    const int  tj   = tau & 31;          // hidden unit
    const bool comb = (l < 16);

    // ---- Weights into registers ----
    const float wih1 = W_ih1[r];
    const float bb1  = b_ih1[r] + b_hh1[r];
    const float bb2  = b_ih2[r] + b_hh2[r];
    const float wl   = W_lin[tj];        // head weight of this thread's task unit
    const float blin = b_lin[0];

    u64 whh1p[Hh / 2], wih2p[Hh / 2], whh2p[Hh / 2];
    {
        const u64* p1 = (const u64*)(W_hh1 + r * Hh);
        const u64* p2 = (const u64*)(W_ih2 + r * Hh);
        const u64* p3 = (const u64*)(W_hh2 + r * Hh);
#pragma unroll
        for (int i = 0; i < Hh / 2; i++) { whh1p[i] = p1[i]; wih2p[i] = p2[i]; whh2p[i] = p3[i]; }
    }

    // ---- Stage input rows ----
#pragma unroll
    for (int e = 0; e < EPB; e++)
        for (int t = r; t < TIN; t += 128)
            sh_in[e][t] = input[(b0 + e) * TIN + t];

    if (comb) { sh_h1[te][tj] = 0.0f; sh_h2[te][tj] = 0.0f; }
    float c1 = 0.0f, c2 = 0.0f;          // cell state of task (te, tj)
    __syncthreads();

    // ================= Teacher-forced phase: 3 barriers/step, no head =================
#pragma unroll 1
    for (int t = 0; t < TFE; t++) {
        // P1: layer-1 gates
#pragma unroll
        for (int e = 0; e < EPB; e++) {
            float x = sh_in[e][t];
            const ulonglong2* hp = (const ulonglong2*)sh_h1[e];
            u64 a0 = 0ull, a1 = 0ull;
#pragma unroll
            for (int i = 0; i < 8; i++) {
                ulonglong2 hv = hp[i];
                a0 = fma2(whh1p[2 * i],     hv.x, a0);
                a1 = fma2(whh1p[2 * i + 1], hv.y, a1);
            }
            u64 s = add2(a0, a1);
            sh_zA[e][r] = fmaf(wih1, x, bb1) + (f2lo(s) + f2hi(s));
        }
        __syncthreads();

        // P2: layer-1 combine (spread over all warps)
        if (comb) {
            float zi = sh_zA[te][tj],          zf = sh_zA[te][Hh + tj];
            float zg = sh_zA[te][2 * Hh + tj], zo = sh_zA[te][3 * Hh + tj];
            float cn = fmaf(sigm(zf), c1, sigm(zi) * tanh_(zg));
            c1 = cn;
            sh_h1[te][tj] = sigm(zo) * tanh_(cn);
        }
        __syncthreads();

        // P3: layer-2 gates
#pragma unroll
        for (int e = 0; e < EPB; e++) {
            const ulonglong2* h1p = (const ulonglong2*)sh_h1[e];
            const ulonglong2* h2p = (const ulonglong2*)sh_h2[e];
            u64 a0 = 0ull, a1 = 0ull, a2 = 0ull, a3 = 0ull;
#pragma unroll
            for (int i = 0; i < 8; i++) {
                ulonglong2 hv1 = h1p[i];
                ulonglong2 hv2 = h2p[i];
                a0 = fma2(wih2p[2 * i],     hv1.x, a0);
                a1 = fma2(wih2p[2 * i + 1], hv1.y, a1);
                a2 = fma2(whh2p[2 * i],     hv2.x, a2);
                a3 = fma2(whh2p[2 * i + 1], hv2.y, a3);
            }
            u64 s = add2(add2(a0, a1), add2(a2, a3));
            sh_zB[e][r] = bb2 + (f2lo(s) + f2hi(s));
        }
        __syncthreads();

        // P4: layer-2 combine; h2 -> SMEM + global history. No barrier (flows into P1).
        if (comb) {
            float zi = sh_zB[te][tj],          zf = sh_zB[te][Hh + tj];
            float zg = sh_zB[te][2 * Hh + tj], zo = sh_zB[te][3 * Hh + tj];
            float cn = fmaf(sigm(zf), c2, sigm(zi) * tanh_(zg));
            c2 = cn;
            float hn = sigm(zo) * tanh_(cn);
            sh_h2[te][tj] = hn;
            H2g[((size_t)(b0 + te) * TFE + t) * Hh + tj] = hn;
        }
    }

    // ================= Gen phase (incl. last TF step t=998): 4 barriers/step =================
    float xf[EPB];
#pragma unroll 1
    for (int t = TFE; t < STEPS; t++) {
        __syncthreads();                 // protects sh_h2 / sh_p from prior P4

        if (t == TFE) {
#pragma unroll
            for (int e = 0; e < EPB; e++) xf[e] = sh_in[e][TFE];
        } else {
            float4 p0 = *(const float4*)sh_p[0];
            float4 p1 = *(const float4*)sh_p[1];
            xf[0] = ((p0.x + p0.y) + (p0.z + p0.w)) + blin;
            xf[1] = ((p1.x + p1.y) + (p1.z + p1.w)) + blin;
            if (r < EPB) out[(size_t)(b0 + r) * STEPS + (t - 1)] = xf[r];
        }

        // P1
#pragma unroll
        for (int e = 0; e < EPB; e++) {
            float x = xf[e];
            const ulonglong2* hp = (const ulonglong2*)sh_h1[e];
            u64 a0 = 0ull, a1 = 0ull;
#pragma unroll
            for (int i = 0; i < 8; i++) {
                ulonglong2 hv = hp[i];
                a0 = fma2(whh1p[2 * i],     hv.x, a0);
                a1 = fma2(whh1p[2 * i + 1], hv.y, a1);
            }
            u64 s = add2(a0, a1);
            sh_zA[e][r] = fmaf(wih1, x, bb1) + (f2lo(s) + f2hi(s));
        }
        __syncthreads();

        // P2
        if (comb) {
            float zi = sh_zA[te][tj],          zf = sh_zA[te][Hh + tj];
            float zg = sh_zA[te][2 * Hh + tj], zo = sh_zA[te][3 * Hh + tj];
            float cn = fmaf(sigm(zf), c1, sigm(zi) * tanh_(zg));
            c1 = cn;
            sh_h1[te][tj] = sigm(zo) * tanh_(cn);
        }
        __syncthreads();

        // P3
#pragma unroll
        for (int e = 0; e < EPB; e++) {
            const ulonglong2* h1p = (const ulonglong2*)sh_h1[e];
            const ulonglong2* h2p = (const ulonglong2*)sh_h2[e];
            u64 a0 = 0ull, a1 = 0ull, a2 = 0ull, a3 = 0ull;
#pragma unroll
            for (int i = 0; i < 8; i++) {
                ulonglong2 hv1 = h1p[i];
                ulonglong2 hv2 = h2p[i];
                a0 = fma2(wih2p[2 * i],     hv1.x, a0);
                a1 = fma2(wih2p[2 * i + 1], hv1.y, a1);
                a2 = fma2(whh2p[2 * i],     hv2.x, a2);
                a3 = fma2(whh2p[2 * i + 1], hv2.y, a3);
            }
            u64 s = add2(add2(a0, a1), add2(a2, a3));
            sh_zB[e][r] = bb2 + (f2lo(s) + f2hi(s));
        }
        __syncthreads();

        // P4 + head partials (3 shfls within 8-lane groups)
        if (comb) {
            float zi = sh_zB[te][tj],          zf = sh_zB[te][Hh + tj];
            float zg = sh_zB[te][2 * Hh + tj], zo = sh_zB[te][3 * Hh + tj];
            float cn = fmaf(sigm(zf), c2, sigm(zi) * tanh_(zg));
            c2 = cn;
            float hn = sigm(zo) * tanh_(cn);
            sh_h2[te][tj] = hn;

            float p = wl * hn;
            p += __shfl_xor_sync(0x0000ffffu, p, 1);
            p += __shfl_xor_sync(0x0000ffffu, p, 2);
            p += __shfl_xor_sync(0x0000ffffu, p, 4);
            if ((l & 7) == 0) sh_p[te][w] = p;     // lanes 0 (e0) and 8 (e1)
        }
    }

    // Final output (t = STEPS-1)
    __syncthreads();
    {
        float4 p0 = *(const float4*)sh_p[0];
        float4 p1 = *(const float4*)sh_p[1];
        float o0 = ((p0.x + p0.y) + (p0.z + p0.w)) + blin;
        float o1 = ((p1.x + p1.y) + (p1.z + p1.w)) + blin;
        if (r == 0) out[(size_t)(b0 + 0) * STEPS + (STEPS - 1)] = o0;
        if (r == 1) out[(size_t)(b0 + 1) * STEPS + (STEPS - 1)] = o1;
    }
}

// Apply linear head to the stored TF h2 history: out[b][t] = W_lin @ H2g[b][t] + b_lin
__global__ __launch_bounds__(256) void head_kernel(
    const float* __restrict__ W_lin, const float* __restrict__ b_lin,
    float* __restrict__ out)
{
    const int b = blockIdx.x;
    float4 wv[8];
    const float4* wp = (const float4*)W_lin;
#pragma unroll
    for (int i = 0; i < 8; i++) wv[i] = wp[i];
    const float bl = b_lin[0];

    for (int t = threadIdx.x; t < TFE; t += 256) {
        const float4* hp = (const float4*)(H2g + ((size_t)b * TFE + t) * Hh);
        float acc = bl;
#pragma unroll
        for (int i = 0; i < 8; i++) {
            float4 h = hp[i];
            acc += wv[i].x * h.x + wv[i].y * h.y + wv[i].z * h.z + wv[i].w * h.w;
        }
        out[(size_t)b * STEPS + t] = acc;
    }
}

extern "C" void kernel_launch(void* const* d_in, const int* in_sizes, int n_in,
                              void* d_out, int out_size) {
    const float* input = (const float*)d_in[0];
    const float* W_ih1 = (const float*)d_in[1];
    const float* W_hh1 = (const float*)d_in[2];
    const float* b_ih1 = (const float*)d_in[3];
    const float* b_hh1 = (const float*)d_in[4];
    const float* W_ih2 = (const float*)d_in[5];
    const float* W_hh2 = (const float*)d_in[6];
    const float* b_ih2 = (const float*)d_in[7];
    const float* b_hh2 = (const float*)d_in[8];
    const float* W_lin = (const float*)d_in[9];
    const float* b_lin = (const float*)d_in[10];
    float* out = (float*)d_out;

    lstm_seq_kernel<<<BATCH / EPB, 128>>>(input, W_ih1, W_hh1, b_ih1, b_hh1,
                                          W_ih2, W_hh2, b_ih2, b_hh2,
                                          W_lin, b_lin, out);
    head_kernel<<<BATCH, 256>>>(W_lin, b_lin, out);
}